// round 2
// baseline (speedup 1.0000x reference)
#include <cuda_runtime.h>
#include <math.h>

#define Bn   16
#define Cn   256
#define Hn   48
#define Wn   48
#define HWn  2304
#define KK   49

// Scratch (device globals, zero-initialized at module load; padding rows are
// NEVER written, so they stay zero across graph replays).
__device__ float g_z[Bn * Cn];                              // GAP [B,C]
__device__ __align__(16) float g_fs[Bn * HWn];              // channel sum
__device__ float g_basis[40 * KK];                          // bases
__device__ __align__(16) float g_coeffP[3 * Bn * 16 * Cn];  // padded coeffs
__device__ float g_G[3 * Bn * 256];                         // padded Gram/C
__device__ float g_s1[3 * Bn * 16];                         // padded colmean/C
__device__ __align__(16) float g_UP[(size_t)Bn * 3 * 16 * HWn]; // padded basis convs
__device__ __align__(16) float g_mu[Bn * 3 * HWn];          // per-pixel mean
__device__ __align__(16) float g_rs[Bn * 3 * HWn];          // per-pixel rstd

// ---------------------------------------------------------------------------
// k_prep: block 0 computes all 40 basis kernels; blocks 1..144 zero g_fs
__global__ void k_prep(const float* __restrict__ rw1, const float* __restrict__ rb1,
                       const float* __restrict__ rw2, const float* __restrict__ rb2) {
    int tid = threadIdx.x;
    if (blockIdx.x > 0) {
        int i = (blockIdx.x - 1) * 256 + tid;   // 144*256 = 36864 = Bn*HWn
        g_fs[i] = 0.f;
        return;
    }
    __shared__ float r[KK], th[KK];
    if (tid < KK) {
        int i = tid / 7, j = tid % 7;
        float gy = (float)i - 3.f, gx = (float)j - 3.f;
        r[tid] = sqrtf(gx * gx + gy * gy + 1e-8f);
        th[tid] = atan2f(gy, gx);
    }
    __syncthreads();

    // Gaussian bases: inv (tid 0..7), eq (tid 8..23)
    if (tid < 24) {
        bool inv = tid < 8;
        int i = inv ? tid : (tid - 8);
        int combo = i % 9;
        int d = combo / 3, si = combo % 3;
        float sig = inv ? (4.f + 2.f * (float)si) : (1.f + (float)si);
        float psi[KK];
        float ss = 0.f;
        for (int c = 0; c < KK; ++c) {
            float u = r[c] / sig;
            float g = expf(-0.5f * u * u);
            float p = (d == 0) ? 1.f : ((d == 1) ? u : (u * u - 1.f));
            psi[c] = p * g;
            ss += psi[c] * psi[c];
        }
        float inorm = 1.f / sqrtf(ss + 1e-8f);
        int gi = inv ? tid : (8 + i);
        for (int c = 0; c < KK; ++c) g_basis[gi * KK + c] = psi[c] * inorm;
    }

    // Harmonic bases: one thread per cell
    if (tid < KK) {
        float rad0 = rb2[0], rad1 = rb2[1];
        for (int h = 0; h < 32; ++h) {
            float t = tanhf(r[tid] * rw1[h] + rb1[h]);
            rad0 += t * rw2[h * 2 + 0];
            rad1 += t * rw2[h * 2 + 1];
        }
        for (int l = 0; l < 8; ++l) {
            float o = (float)(l / 2 + 1);
            float a = (l & 1) ? sinf(o * th[tid]) : cosf(o * th[tid]);
            g_basis[(24 + l) * KK + tid]     = rad0 * a;
            g_basis[(24 + 8 + l) * KK + tid] = rad1 * a;
        }
    }
}

// ---------------------------------------------------------------------------
// k_reduce: z[b,c] = mean_HW(feature), fs[b,p] = sum_C(feature)
__global__ void k_reduce(const float* __restrict__ feat) {
    int b = blockIdx.y, chunk = blockIdx.x;
    int tid = threadIdx.x;
    int lane = tid & 31, wid = tid >> 5;
    __shared__ float zsum[16][8];

    float facc[9];
#pragma unroll
    for (int k = 0; k < 9; ++k) facc[k] = 0.f;

    const float* fb = feat + ((size_t)b * Cn + (size_t)chunk * 16) * HWn;
    for (int c = 0; c < 16; ++c) {
        const float* fp = fb + (size_t)c * HWn;
        float csum = 0.f;
#pragma unroll
        for (int k = 0; k < 9; ++k) {
            float v = fp[tid + 256 * k];
            facc[k] += v;
            csum += v;
        }
#pragma unroll
        for (int o = 16; o; o >>= 1) csum += __shfl_xor_sync(0xffffffffu, csum, o);
        if (lane == 0) zsum[c][wid] = csum;
    }
    __syncthreads();
    if (tid < 16) {
        float s = 0.f;
#pragma unroll
        for (int w = 0; w < 8; ++w) s += zsum[tid][w];
        g_z[b * Cn + chunk * 16 + tid] = s * (1.f / (float)HWn);
    }
#pragma unroll
    for (int k = 0; k < 9; ++k)
        atomicAdd(&g_fs[b * HWn + tid + 256 * k], facc[k]);
}

// ---------------------------------------------------------------------------
// k_mlp: fused hidden + coeff + stats per (branch, b). grid (3, B), block 288
__global__ void k_mlp(const float* __restrict__ w1i, const float* __restrict__ b1i,
                      const float* __restrict__ w2i, const float* __restrict__ b2i,
                      const float* __restrict__ w1e, const float* __restrict__ b1e,
                      const float* __restrict__ w2e, const float* __restrict__ b2e,
                      const float* __restrict__ w1c, const float* __restrict__ b1c,
                      const float* __restrict__ w2c, const float* __restrict__ b2c) {
    int br = blockIdx.x, b = blockIdx.y, tid = threadIdx.x;
    int N = (br == 0) ? 8 : 16;
    int NC = N * Cn;
    const float* w1 = (br == 0) ? w1i : ((br == 1) ? w1e : w1c);
    const float* b1 = (br == 0) ? b1i : ((br == 1) ? b1e : b1c);
    const float* w2 = (br == 0) ? w2i : ((br == 1) ? w2e : w2c);
    const float* b2 = (br == 0) ? b2i : ((br == 1) ? b2e : b2c);

    __shared__ float zz[Cn];
    __shared__ float hh[64];
    __shared__ float sc[16 * Cn];  // 16 KB

    if (tid < Cn) zz[tid] = g_z[b * Cn + tid];
    __syncthreads();

    // hidden: 64 threads, coalesced w1 reads, 4 accumulators
    if (tid < 64) {
        float a0 = 0.f, a1 = 0.f, a2 = 0.f, a3 = 0.f;
#pragma unroll 4
        for (int c = 0; c < Cn; c += 4) {
            a0 += zz[c + 0] * w1[(c + 0) * 64 + tid];
            a1 += zz[c + 1] * w1[(c + 1) * 64 + tid];
            a2 += zz[c + 2] * w1[(c + 2) * 64 + tid];
            a3 += zz[c + 3] * w1[(c + 3) * 64 + tid];
        }
        hh[tid] = fmaxf(a0 + a1 + a2 + a3 + b1[tid], 0.f);
    }
    __syncthreads();

    // coeff: thread = channel
    if (tid < Cn) {
        int c = tid;
        for (int n = 0; n < N; ++n) {
            float acc = b2[n * Cn + c];
#pragma unroll 8
            for (int h2 = 0; h2 < 64; ++h2)
                acc += hh[h2] * w2[(size_t)h2 * NC + n * Cn + c];
            sc[n * Cn + c] = acc;
            g_coeffP[((size_t)(br * Bn + b) * 16 + n) * Cn + c] = acc;
        }
    }
    __syncthreads();

    // stats: Gram/C (stride-16 padded layout) and colmean/C
    if (tid < N * N) {
        int n = tid / N, m = tid % N;
        float acc = 0.f;
        for (int c = 0; c < Cn; ++c) acc += sc[n * Cn + c] * sc[m * Cn + c];
        g_G[(br * Bn + b) * 256 + n * 16 + m] = acc * (1.f / (float)Cn);
    } else if (tid < N * N + N) {
        int n = tid - N * N;
        float acc = 0.f;
        for (int c = 0; c < Cn; ++c) acc += sc[n * Cn + c];
        g_s1[(br * Bn + b) * 16 + n] = acc * (1.f / (float)Cn);
    }
}

// ---------------------------------------------------------------------------
// k_uconv: U[b,br,nl,p] = (fs[b] cross-corr basis[g])[p]. grid (40, B), 256
__global__ void k_uconv() {
    int g = blockIdx.x, b = blockIdx.y, tid = threadIdx.x;
    int br = (g < 8) ? 0 : ((g < 24) ? 1 : 2);
    int nl = g - ((br == 0) ? 0 : ((br == 1) ? 8 : 24));
    __shared__ float fp[54 * 54];
    __shared__ float bs[KK];
    if (tid < KK) bs[tid] = g_basis[g * KK + tid];
    for (int i = tid; i < 54 * 54; i += 256) {
        int row = i / 54, col = i % 54;
        int y = row - 3, x = col - 3;
        fp[i] = (y >= 0 && y < Hn && x >= 0 && x < Wn) ? g_fs[b * HWn + y * Wn + x] : 0.f;
    }
    __syncthreads();
    float* up = g_UP + (((size_t)b * 3 + br) * 16 + nl) * HWn;
#pragma unroll
    for (int k = 0; k < 9; ++k) {
        int p = tid + 256 * k;
        int y = p / Wn, x = p % Wn;
        float acc = 0.f;
#pragma unroll
        for (int dy = 0; dy < 7; ++dy)
#pragma unroll
            for (int dx = 0; dx < 7; ++dx)
                acc += fp[(y + dy) * 54 + x + dx] * bs[dy * 7 + dx];
        up[p] = acc;
    }
}

// ---------------------------------------------------------------------------
// k_pixstats: per-pixel LN mean & rstd via Gram quadratic form.
// grid (3, B), block 576 (576*4 = 2304 pixels)
__global__ void k_pixstats() {
    int br = blockIdx.x, b = blockIdx.y, tid = threadIdx.x;
    __shared__ float sG[256];
    __shared__ float sm[16];
    if (tid < 256) sG[tid] = g_G[(br * Bn + b) * 256 + tid];
    if (tid < 16)  sm[tid] = g_s1[(br * Bn + b) * 16 + tid];
    __syncthreads();

    int p0 = tid * 4;
    const float* ub = g_UP + ((size_t)b * 3 + br) * 16 * HWn;
    float4 u[16];
#pragma unroll
    for (int n = 0; n < 16; ++n)
        u[n] = *(const float4*)(ub + (size_t)n * HWn + p0);

    float4 m = make_float4(0.f, 0.f, 0.f, 0.f);
#pragma unroll
    for (int n = 0; n < 16; ++n) {
        float s = sm[n];
        m.x += s * u[n].x; m.y += s * u[n].y; m.z += s * u[n].z; m.w += s * u[n].w;
    }
    float4 q = make_float4(0.f, 0.f, 0.f, 0.f);
#pragma unroll
    for (int n = 0; n < 16; ++n) {
        float4 t = make_float4(0.f, 0.f, 0.f, 0.f);
#pragma unroll
        for (int mm = 0; mm < 16; ++mm) {
            float gg = sG[n * 16 + mm];
            t.x += gg * u[mm].x; t.y += gg * u[mm].y; t.z += gg * u[mm].z; t.w += gg * u[mm].w;
        }
        q.x += t.x * u[n].x; q.y += t.y * u[n].y; q.z += t.z * u[n].z; q.w += t.w * u[n].w;
    }
    float4 r;
    r.x = rsqrtf(fmaxf(q.x - m.x * m.x, 0.f) + 1e-5f);
    r.y = rsqrtf(fmaxf(q.y - m.y * m.y, 0.f) + 1e-5f);
    r.z = rsqrtf(fmaxf(q.z - m.z * m.z, 0.f) + 1e-5f);
    r.w = rsqrtf(fmaxf(q.w - m.w * m.w, 0.f) + 1e-5f);

    *(float4*)(g_mu + (b * 3 + br) * HWn + p0) = m;
    *(float4*)(g_rs + (b * 3 + br) * HWn + p0) = r;
}

// ---------------------------------------------------------------------------
// k_main: fused GEMM + LN apply + store. grid (3 px-chunks, B, 6), block 192.
// blockIdx.z = br*2 + cgroup (128 channels each). Thread owns 4 consec pixels.
__global__ void k_main(const float* __restrict__ lig, const float* __restrict__ lib,
                       const float* __restrict__ leg, const float* __restrict__ leb,
                       const float* __restrict__ lcg, const float* __restrict__ lcb,
                       float* __restrict__ out) {
    int chunk = blockIdx.x, b = blockIdx.y, bz = blockIdx.z;
    int br = bz >> 1, cg = bz & 1;
    int c0 = cg * 128;
    int tid = threadIdx.x;

    const float* lng = (br == 0) ? lig : ((br == 1) ? leg : lcg);
    const float* lnb = (br == 0) ? lib : ((br == 1) ? leb : lcb);

    __shared__ float scf[16 * 128];
    __shared__ float sg[128], sb[128];
    for (int i = tid; i < 16 * 128; i += 192) {
        int n = i >> 7, c = i & 127;
        scf[i] = g_coeffP[((size_t)(br * Bn + b) * 16 + n) * Cn + c0 + c];
    }
    if (tid < 128) { sg[tid] = lng[c0 + tid]; sb[tid] = lnb[c0 + tid]; }
    __syncthreads();

    int p0 = chunk * 768 + tid * 4;
    const float* ub = g_UP + ((size_t)b * 3 + br) * 16 * HWn;
    float4 u[16];
#pragma unroll
    for (int n = 0; n < 16; ++n)
        u[n] = *(const float4*)(ub + (size_t)n * HWn + p0);

    float4 m = *(const float4*)(g_mu + (b * 3 + br) * HWn + p0);
    float4 r = *(const float4*)(g_rs + (b * 3 + br) * HWn + p0);

    float* ob = out + (size_t)br * Bn * Cn * HWn + (size_t)b * Cn * HWn
                    + (size_t)c0 * HWn + p0;
#pragma unroll 2
    for (int c = 0; c < 128; ++c) {
        float4 v = make_float4(0.f, 0.f, 0.f, 0.f);
#pragma unroll
        for (int n = 0; n < 16; ++n) {
            float w = scf[n * 128 + c];
            v.x += w * u[n].x; v.y += w * u[n].y; v.z += w * u[n].z; v.w += w * u[n].w;
        }
        float A = sg[c], Bc = sb[c];
        float4 o;
        o.x = (v.x - m.x) * r.x * A + Bc;
        o.y = (v.y - m.y) * r.y * A + Bc;
        o.z = (v.z - m.z) * r.z * A + Bc;
        o.w = (v.w - m.w) * r.w * A + Bc;
        *(float4*)(ob + (size_t)c * HWn) = o;
    }
}

// ---------------------------------------------------------------------------
extern "C" void kernel_launch(void* const* d_in, const int* in_sizes, int n_in,
                              void* d_out, int out_size) {
    const float* feat = (const float*)d_in[0];
    const float* iw1 = (const float*)d_in[1];
    const float* ib1 = (const float*)d_in[2];
    const float* iw2 = (const float*)d_in[3];
    const float* ib2 = (const float*)d_in[4];
    const float* ew1 = (const float*)d_in[5];
    const float* eb1 = (const float*)d_in[6];
    const float* ew2 = (const float*)d_in[7];
    const float* eb2 = (const float*)d_in[8];
    const float* cw1 = (const float*)d_in[9];
    const float* cb1 = (const float*)d_in[10];
    const float* cw2 = (const float*)d_in[11];
    const float* cb2 = (const float*)d_in[12];
    const float* rw1 = (const float*)d_in[13];
    const float* rb1 = (const float*)d_in[14];
    const float* rw2 = (const float*)d_in[15];
    const float* rb2 = (const float*)d_in[16];
    const float* lig = (const float*)d_in[17];
    const float* lib = (const float*)d_in[18];
    const float* leg = (const float*)d_in[19];
    const float* leb = (const float*)d_in[20];
    const float* lcg = (const float*)d_in[21];
    const float* lcb = (const float*)d_in[22];
    float* out = (float*)d_out;

    k_prep<<<145, 256>>>(rw1, rb1, rw2, rb2);
    k_reduce<<<dim3(16, Bn), 256>>>(feat);
    k_mlp<<<dim3(3, Bn), 288>>>(iw1, ib1, iw2, ib2, ew1, eb1, ew2, eb2, cw1, cb1, cw2, cb2);
    k_uconv<<<dim3(40, Bn), 256>>>();
    k_pixstats<<<dim3(3, Bn), 576>>>();
    k_main<<<dim3(3, Bn, 6), 192>>>(lig, lib, leg, leb, lcg, lcb, out);
}

// round 7
// speedup vs baseline: 1.1554x; 1.1554x over previous
#include <cuda_runtime.h>
#include <math.h>

#define Bn   16
#define Cn   256
#define Hn   48
#define Wn   48
#define HWn  2304
#define KK   49

typedef unsigned long long ull;

// f32x2 packed-math macros (sm_103a FFMA2 path)
#define FMA2(d,a,b,c) asm("fma.rn.f32x2 %0, %1, %2, %3;" : "=l"(d) : "l"(a), "l"(b), "l"(c))
#define MUL2(d,a,b)   asm("mul.rn.f32x2 %0, %1, %2;"     : "=l"(d) : "l"(a), "l"(b))
#define PK2(d,lo,hi)  asm("mov.b64 %0, {%1, %2};"        : "=l"(d) : "f"(lo), "f"(hi))
#define UPK2(lo,hi,s) asm("mov.b64 {%0, %1}, %2;"        : "=f"(lo), "=f"(hi) : "l"(s))

// Scratch (device globals, zero-initialized at load; padding rows never written)
__device__ float g_z[Bn * Cn];
__device__ __align__(16) float g_fs[Bn * HWn];
__device__ float g_basis[40 * KK];
__device__ __align__(16) float g_coeffP[3 * Bn * 16 * Cn];   // padded [br,b,16,C]
__device__ float g_G[3 * Bn * 256];                          // padded Gram/C (n*16+m)
__device__ float g_s1[3 * Bn * 16];                          // padded colmean/C
__device__ __align__(16) float g_UP[(size_t)Bn * 3 * 16 * HWn]; // padded basis convs

// ---------------------------------------------------------------------------
// k_prep: block 0 computes the 40 basis kernels; blocks 1..144 zero g_fs
__global__ void k_prep(const float* __restrict__ rw1, const float* __restrict__ rb1,
                       const float* __restrict__ rw2, const float* __restrict__ rb2) {
    int tid = threadIdx.x;
    if (blockIdx.x > 0) {
        int i = (blockIdx.x - 1) * 256 + tid;
        g_fs[i] = 0.f;
        return;
    }
    __shared__ float r[KK], th[KK];
    if (tid < KK) {
        int i = tid / 7, j = tid % 7;
        float gy = (float)i - 3.f, gx = (float)j - 3.f;
        r[tid] = sqrtf(gx * gx + gy * gy + 1e-8f);
        th[tid] = atan2f(gy, gx);
    }
    __syncthreads();

    if (tid < 24) {
        bool inv = tid < 8;
        int i = inv ? tid : (tid - 8);
        int combo = i % 9;
        int d = combo / 3, si = combo % 3;
        float sig = inv ? (4.f + 2.f * (float)si) : (1.f + (float)si);
        float psi[KK];
        float ss = 0.f;
        for (int c = 0; c < KK; ++c) {
            float u = r[c] / sig;
            float g = expf(-0.5f * u * u);
            float p = (d == 0) ? 1.f : ((d == 1) ? u : (u * u - 1.f));
            psi[c] = p * g;
            ss += psi[c] * psi[c];
        }
        float inorm = 1.f / sqrtf(ss + 1e-8f);
        int gi = inv ? tid : (8 + i);
        for (int c = 0; c < KK; ++c) g_basis[gi * KK + c] = psi[c] * inorm;
    }

    if (tid < KK) {
        float rad0 = rb2[0], rad1 = rb2[1];
        for (int h = 0; h < 32; ++h) {
            float t = tanhf(r[tid] * rw1[h] + rb1[h]);
            rad0 += t * rw2[h * 2 + 0];
            rad1 += t * rw2[h * 2 + 1];
        }
        for (int l = 0; l < 8; ++l) {
            float o = (float)(l / 2 + 1);
            float a = (l & 1) ? sinf(o * th[tid]) : cosf(o * th[tid]);
            g_basis[(24 + l) * KK + tid]     = rad0 * a;
            g_basis[(24 + 8 + l) * KK + tid] = rad1 * a;
        }
    }
}

// ---------------------------------------------------------------------------
// k_reduce: z[b,c] = mean_HW, fs[b,p] = sum_C.  grid (16,B), block 288, float4
__global__ void k_reduce(const float* __restrict__ feat) {
    int b = blockIdx.y, chunk = blockIdx.x, tid = threadIdx.x;
    int lane = tid & 31, w = tid >> 5;           // 9 warps
    __shared__ float zs[16][9];

    float4 f0 = make_float4(0.f, 0.f, 0.f, 0.f);
    float4 f1 = make_float4(0.f, 0.f, 0.f, 0.f);
    const float4* fb = (const float4*)(feat + ((size_t)b * Cn + chunk * 16) * HWn);
    for (int c = 0; c < 16; ++c) {
        const float4* fp = fb + (size_t)c * (HWn / 4);
        float4 a = fp[tid];
        float4 d = fp[tid + 288];
        f0.x += a.x; f0.y += a.y; f0.z += a.z; f0.w += a.w;
        f1.x += d.x; f1.y += d.y; f1.z += d.z; f1.w += d.w;
        float cs = a.x + a.y + a.z + a.w + d.x + d.y + d.z + d.w;
#pragma unroll
        for (int o = 16; o; o >>= 1) cs += __shfl_xor_sync(0xffffffffu, cs, o);
        if (lane == 0) zs[c][w] = cs;
    }
    __syncthreads();
    if (tid < 16) {
        float s = 0.f;
#pragma unroll
        for (int i = 0; i < 9; ++i) s += zs[tid][i];
        g_z[b * Cn + chunk * 16 + tid] = s * (1.f / (float)HWn);
    }
    float* fsb = g_fs + b * HWn;
    atomicAdd(&fsb[4 * tid + 0], f0.x);
    atomicAdd(&fsb[4 * tid + 1], f0.y);
    atomicAdd(&fsb[4 * tid + 2], f0.z);
    atomicAdd(&fsb[4 * tid + 3], f0.w);
    atomicAdd(&fsb[1152 + 4 * tid + 0], f1.x);
    atomicAdd(&fsb[1152 + 4 * tid + 1], f1.y);
    atomicAdd(&fsb[1152 + 4 * tid + 2], f1.z);
    atomicAdd(&fsb[1152 + 4 * tid + 3], f1.w);
}

// ---------------------------------------------------------------------------
// k_mlp: fused hidden + coeff + stats, templated on N to keep acc[] in regs
template <int N>
__device__ __forceinline__ void mlp_body(
    int br, int b, int tid,
    const float* __restrict__ w1, const float* __restrict__ b1,
    const float* __restrict__ w2, const float* __restrict__ b2,
    float* zz, float (*hp)[64], float* hh, float* sc) {
    const int NC = N * Cn;
    if (tid < Cn) zz[tid] = g_z[b * Cn + tid];
    __syncthreads();
    if (tid < 256) {
        int j = tid & 63, s = tid >> 6;
        float a = 0.f;
        const float* wp = w1 + (size_t)(64 * s) * 64 + j;
#pragma unroll 8
        for (int c = 0; c < 64; ++c) a += zz[64 * s + c] * wp[c * 64];
        hp[s][j] = a;
    }
    __syncthreads();
    if (tid < 64)
        hh[tid] = fmaxf(hp[0][tid] + hp[1][tid] + hp[2][tid] + hp[3][tid] + b1[tid], 0.f);
    __syncthreads();
    if (tid < Cn) {
        int c = tid;
        float acc[N];
#pragma unroll
        for (int n = 0; n < N; ++n) acc[n] = b2[n * Cn + c];
        for (int h2 = 0; h2 < 64; ++h2) {
            float hv = hh[h2];
            const float* wp = w2 + (size_t)h2 * NC + c;
#pragma unroll
            for (int n = 0; n < N; ++n) acc[n] += hv * wp[n * Cn];
        }
#pragma unroll
        for (int n = 0; n < N; ++n) {
            sc[n * Cn + c] = acc[n];
            g_coeffP[((size_t)(br * Bn + b) * 16 + n) * Cn + c] = acc[n];
        }
    }
    __syncthreads();
    if (tid < N * N) {
        int n = tid / N, m = tid % N;
        float a = 0.f;
#pragma unroll 4
        for (int c = 0; c < Cn; ++c) a += sc[n * Cn + c] * sc[m * Cn + c];
        g_G[(br * Bn + b) * 256 + n * 16 + m] = a * (1.f / (float)Cn);
    } else if (tid < N * N + N) {
        int n = tid - N * N;
        float a = 0.f;
#pragma unroll 4
        for (int c = 0; c < Cn; ++c) a += sc[n * Cn + c];
        g_s1[(br * Bn + b) * 16 + n] = a * (1.f / (float)Cn);
    }
}

__global__ void k_mlp(const float* __restrict__ w1i, const float* __restrict__ b1i,
                      const float* __restrict__ w2i, const float* __restrict__ b2i,
                      const float* __restrict__ w1e, const float* __restrict__ b1e,
                      const float* __restrict__ w2e, const float* __restrict__ b2e,
                      const float* __restrict__ w1c, const float* __restrict__ b1c,
                      const float* __restrict__ w2c, const float* __restrict__ b2c) {
    int br = blockIdx.x, b = blockIdx.y, tid = threadIdx.x;
    __shared__ float zz[Cn];
    __shared__ float hp[4][64];
    __shared__ float hh[64];
    __shared__ float sc[16 * Cn];
    if (br == 0)
        mlp_body<8>(0, b, tid, w1i, b1i, w2i, b2i, zz, hp, hh, sc);
    else if (br == 1)
        mlp_body<16>(1, b, tid, w1e, b1e, w2e, b2e, zz, hp, hh, sc);
    else
        mlp_body<16>(2, b, tid, w1c, b1c, w2c, b2c, zz, hp, hh, sc);
}

// ---------------------------------------------------------------------------
// k_uconv: register-blocked 7x7 conv of fs with each basis. grid (40,B), 192
__global__ void k_uconv() {
    int g = blockIdx.x, b = blockIdx.y, tid = threadIdx.x;
    int br = (g < 8) ? 0 : ((g < 24) ? 1 : 2);
    int nl = g - ((br == 0) ? 0 : ((br == 1) ? 8 : 24));
    __shared__ float fp[54 * 54];
    __shared__ float bs[KK];
    if (tid < KK) bs[tid] = g_basis[g * KK + tid];
    for (int i = tid; i < 54 * 54; i += 192) {
        int row = i / 54, col = i % 54;
        int y = row - 3, x = col - 3;
        fp[i] = (y >= 0 && y < Hn && x >= 0 && x < Wn) ? g_fs[b * HWn + y * Wn + x] : 0.f;
    }
    __syncthreads();

    int x = tid % 48, yg0 = tid / 48;   // yg0 in 0..3
    float* up = g_UP + (((size_t)b * 3 + br) * 16 + nl) * HWn;
#pragma unroll
    for (int it = 0; it < 3; ++it) {
        int y0 = (yg0 + 4 * it) * 4;    // 4 vertically adjacent outputs
        float a0 = 0.f, a1 = 0.f, a2 = 0.f, a3 = 0.f;
#pragma unroll
        for (int ri = 0; ri < 10; ++ri) {
            float t[7];
#pragma unroll
            for (int dx = 0; dx < 7; ++dx) t[dx] = fp[(y0 + ri) * 54 + x + dx];
#pragma unroll
            for (int o = 0; o < 4; ++o) {
                int dy = ri - o;
                if (dy >= 0 && dy < 7) {
                    float s = 0.f;
#pragma unroll
                    for (int dx = 0; dx < 7; ++dx) s += t[dx] * bs[dy * 7 + dx];
                    if (o == 0) a0 += s; else if (o == 1) a1 += s;
                    else if (o == 2) a2 += s; else a3 += s;
                }
            }
        }
        up[(y0 + 0) * Wn + x] = a0;
        up[(y0 + 1) * Wn + x] = a1;
        up[(y0 + 2) * Wn + x] = a2;
        up[(y0 + 3) * Wn + x] = a3;
    }
}

// ---------------------------------------------------------------------------
// k_main: inline LN stats + f32x2 GEMM + store. grid (3,B,3), block 192.
__global__ void __launch_bounds__(192)
k_main(const float* __restrict__ lig, const float* __restrict__ lib,
       const float* __restrict__ leg, const float* __restrict__ leb,
       const float* __restrict__ lcg, const float* __restrict__ lcb,
       float* __restrict__ out) {
    int chunk = blockIdx.x, b = blockIdx.y, br = blockIdx.z;
    int tid = threadIdx.x;

    const float* lng = (br == 0) ? lig : ((br == 1) ? leg : lcg);
    const float* lnb = (br == 0) ? lib : ((br == 1) ? leb : lcb);

    __shared__ ull scf2[16 * Cn];   // dup-packed coeffs (32 KB)
    __shared__ ull sga[Cn], sbb[Cn];
    __shared__ float sG[256];
    __shared__ float sm1[16];

    const float* cf = g_coeffP + (size_t)(br * Bn + b) * 16 * Cn;
    for (int i = tid; i < 16 * Cn; i += 192) {
        float w = cf[i];
        ull p; PK2(p, w, w);
        scf2[i] = p;
    }
    for (int i = tid; i < Cn; i += 192) {
        float A = lng[i], Bc = lnb[i];
        ull pa, pb; PK2(pa, A, A); PK2(pb, Bc, Bc);
        sga[i] = pa; sbb[i] = pb;
        sG[i] = g_G[(br * Bn + b) * 256 + i];
    }
    if (tid < 16) sm1[tid] = g_s1[(br * Bn + b) * 16 + tid];
    __syncthreads();

    int p0 = chunk * 768 + tid * 4;
    const float* ub = g_UP + ((size_t)b * 3 + br) * 16 * HWn;
    ull u[16][2];
#pragma unroll
    for (int n = 0; n < 16; ++n) {
        float4 v4 = *(const float4*)(ub + (size_t)n * HWn + p0);
        PK2(u[n][0], v4.x, v4.y);
        PK2(u[n][1], v4.z, v4.w);
    }

    // LN stats inline: mean and E[x^2] via Gram quadratic form
    ull m0 = 0ull, m1 = 0ull;
#pragma unroll
    for (int n = 0; n < 16; ++n) {
        ull s2; float s = sm1[n]; PK2(s2, s, s);
        FMA2(m0, s2, u[n][0], m0);
        FMA2(m1, s2, u[n][1], m1);
    }
    ull q0 = 0ull, q1 = 0ull;
#pragma unroll
    for (int n = 0; n < 16; ++n) {
        ull t0 = 0ull, t1 = 0ull;
#pragma unroll
        for (int mm = 0; mm < 16; ++mm) {
            ull g2; float gg = sG[n * 16 + mm]; PK2(g2, gg, gg);
            FMA2(t0, g2, u[mm][0], t0);
            FMA2(t1, g2, u[mm][1], t1);
        }
        FMA2(q0, t0, u[n][0], q0);
        FMA2(q1, t1, u[n][1], q1);
    }
    float mx, my, mz, mw, qx, qy, qz, qw;
    UPK2(mx, my, m0); UPK2(mz, mw, m1);
    UPK2(qx, qy, q0); UPK2(qz, qw, q1);
    float rx = rsqrtf(fmaxf(qx - mx * mx, 0.f) + 1e-5f);
    float ry = rsqrtf(fmaxf(qy - my * my, 0.f) + 1e-5f);
    float rz = rsqrtf(fmaxf(qz - mz * mz, 0.f) + 1e-5f);
    float rw = rsqrtf(fmaxf(qw - mw * mw, 0.f) + 1e-5f);
    ull r0, r1, nm0, nm1;
    PK2(r0, rx, ry); PK2(r1, rz, rw);
    PK2(nm0, -mx, -my); PK2(nm1, -mz, -mw);

    float* ob = out + (size_t)br * Bn * Cn * HWn + (size_t)b * Cn * HWn + p0;
#pragma unroll 2
    for (int c = 0; c < Cn; ++c) {
        ull v0 = 0ull, v1 = 0ull;
        const ull* wrow = scf2 + c;
#pragma unroll
        for (int n = 0; n < 16; ++n) {
            ull w = wrow[n * Cn];
            FMA2(v0, w, u[n][0], v0);
            FMA2(v1, w, u[n][1], v1);
        }
        ull A2 = sga[c], B2 = sbb[c];
        ull rA0, rA1, bias0, bias1, o0, o1;
        MUL2(rA0, r0, A2);
        MUL2(rA1, r1, A2);
        FMA2(bias0, nm0, rA0, B2);
        FMA2(bias1, nm1, rA1, B2);
        FMA2(o0, v0, rA0, bias0);
        FMA2(o1, v1, rA1, bias1);
        float4 o;
        UPK2(o.x, o.y, o0);
        UPK2(o.z, o.w, o1);
        *(float4*)(ob + (size_t)c * HWn) = o;
    }
}

// ---------------------------------------------------------------------------
extern "C" void kernel_launch(void* const* d_in, const int* in_sizes, int n_in,
                              void* d_out, int out_size) {
    const float* feat = (const float*)d_in[0];
    const float* iw1 = (const float*)d_in[1];
    const float* ib1 = (const float*)d_in[2];
    const float* iw2 = (const float*)d_in[3];
    const float* ib2 = (const float*)d_in[4];
    const float* ew1 = (const float*)d_in[5];
    const float* eb1 = (const float*)d_in[6];
    const float* ew2 = (const float*)d_in[7];
    const float* eb2 = (const float*)d_in[8];
    const float* cw1 = (const float*)d_in[9];
    const float* cb1 = (const float*)d_in[10];
    const float* cw2 = (const float*)d_in[11];
    const float* cb2 = (const float*)d_in[12];
    const float* rw1 = (const float*)d_in[13];
    const float* rb1 = (const float*)d_in[14];
    const float* rw2 = (const float*)d_in[15];
    const float* rb2 = (const float*)d_in[16];
    const float* lig = (const float*)d_in[17];
    const float* lib = (const float*)d_in[18];
    const float* leg = (const float*)d_in[19];
    const float* leb = (const float*)d_in[20];
    const float* lcg = (const float*)d_in[21];
    const float* lcb = (const float*)d_in[22];
    float* out = (float*)d_out;

    k_prep<<<145, 256>>>(rw1, rb1, rw2, rb2);
    k_reduce<<<dim3(16, Bn), 288>>>(feat);
    k_mlp<<<dim3(3, Bn), 288>>>(iw1, ib1, iw2, ib2, ew1, eb1, ew2, eb2, cw1, cb1, cw2, cb2);
    k_uconv<<<dim3(40, Bn), 192>>>();
    k_main<<<dim3(3, Bn, 3), 192>>>(lig, lib, leg, leb, lcg, lcb, out);
}